// round 8
// baseline (speedup 1.0000x reference)
#include <cuda_runtime.h>
#include <math.h>

// Problem constants
#define N_IMG 4
#define C_DIM 256
#define H_DIM 50
#define W_DIM 50
#define HW (H_DIM * W_DIM)
#define PH 7
#define PW 7
#define NBINS (PH * PW)
#define N_ROI 1024
#define OUT_PER_ROI (C_DIM * NBINS)   // 12544 floats
#define HALF_C 128
#define SPATIAL_SCALE 0.0625f
#define ROW_STRIDE (W_DIM * C_DIM)    // floats per h-row in NHWC

// fl(1/7) in fp32 — XLA rewrites (x / 7) into (x * fl(1/7)); we must match it.
#define RCP_7 0.14285714924335479736328125f

// Scratch: x transposed to [N][H][W][C] (channels-last) = 10.24 MB
__device__ float g_xt[N_IMG * HW * C_DIM];

// Precomputed per-roi geometry (ints, computed once with exact XLA numerics)
__device__ int g_boff[N_ROI];        // image base offset in floats
__device__ int g_hs[N_ROI * PH];
__device__ int g_he[N_ROI * PH];
__device__ int g_ws[N_ROI * PW];
__device__ int g_we[N_ROI * PW];

// ---------------------------------------------------------------------------
// Transpose NCHW -> NHWC via 32x32 smem tiles.
// Block (0,0,0) additionally precomputes all roi bin edges (1024 threads =
// 1024 rois) — zero extra launch, exact XLA numerics isolated here.
// ---------------------------------------------------------------------------
__global__ void __launch_bounds__(1024) transpose_kernel(const float* __restrict__ x,
                                                         const float* __restrict__ rois) {
    __shared__ float tile[32][33];

    if (blockIdx.x == 0 && blockIdx.y == 0 && blockIdx.z == 0) {
        const int roi = threadIdx.y * 32 + threadIdx.x;   // 0..1023
        const float* r = rois + roi * 5;
        const int b  = (int)r[0];
        const int xs = (int)rintf(__fmul_rn(r[1], SPATIAL_SCALE));
        const int ys = (int)rintf(__fmul_rn(r[2], SPATIAL_SCALE));
        const int xe = (int)rintf(__fmul_rn(r[3], SPATIAL_SCALE));
        const int ye = (int)rintf(__fmul_rn(r[4], SPATIAL_SCALE));
        const float rw = (float)max(xe - xs + 1, 1);
        const float rh = (float)max(ye - ys + 1, 1);
        const float bh = __fmul_rn(rh, RCP_7);   // XLA reciprocal-multiply
        const float bw = __fmul_rn(rw, RCP_7);

        g_boff[roi] = b * (HW * C_DIM);
        #pragma unroll
        for (int p = 0; p < PH; ++p) {
            int hs = (int)floorf(__fmul_rn((float)p,        bh)) + ys;
            int he = (int)ceilf (__fmul_rn((float)p + 1.0f, bh)) + ys;
            int ws = (int)floorf(__fmul_rn((float)p,        bw)) + xs;
            int we = (int)ceilf (__fmul_rn((float)p + 1.0f, bw)) + xs;
            g_hs[roi * PH + p] = min(max(hs, 0), H_DIM);
            g_he[roi * PH + p] = min(max(he, 0), H_DIM);
            g_ws[roi * PW + p] = min(max(ws, 0), W_DIM);
            g_we[roi * PW + p] = min(max(we, 0), W_DIM);
        }
    }

    const int n   = blockIdx.z;
    const int hw0 = blockIdx.x * 32;
    const int c0b = blockIdx.y * 32;
    {
        const int c  = c0b + threadIdx.y;
        const int hw = hw0 + threadIdx.x;
        if (hw < HW) {
            tile[threadIdx.y][threadIdx.x] = x[(n * C_DIM + c) * HW + hw];
        }
    }
    __syncthreads();
    {
        const int hw = hw0 + threadIdx.y;
        const int c  = c0b + threadIdx.x;
        if (hw < HW) {
            g_xt[(n * HW + hw) * C_DIM + c] = tile[threadIdx.x][threadIdx.y];
        }
    }
}

// ---------------------------------------------------------------------------
// RoI max pooling, separable: one block per (roi, ph, channel-half).
// Grid = 1024 x 7 x 2. Block = 256 threads = 8 w-warps x 32 ch-lanes
// (float4 -> 128 channels per half).
//
// Phase 1: column h-max over rows [hs,he) for every w in [ws0,we6), each
//          input cell read from L1/L2 exactly ONCE; stored to smem [w][c].
// Phase 2: per-bin w-max read from smem (conflict-free LDS.128).
// Phase 3: stage [c][pw] in (reused) smem, coalesced dump to gmem.
// max is associative -> bit-exact vs single-pass 2D max.
// ---------------------------------------------------------------------------
__global__ void __launch_bounds__(256, 8) roipool_kernel(float* __restrict__ out) {
    __shared__ float s_buf[W_DIM * HALF_C];   // 25600 B; reused for staging

    const int roi  = blockIdx.x;
    const int ph   = blockIdx.y;
    const int half = blockIdx.z;

    const int boff = __ldg(&g_boff[roi]);
    const int hs   = __ldg(&g_hs[roi * PH + ph]);
    const int he   = __ldg(&g_he[roi * PH + ph]);
    const int ws0  = __ldg(&g_ws[roi * PW + 0]);
    const int we6  = __ldg(&g_we[roi * PW + PW - 1]);

    const int lane = threadIdx.x & 31;   // 32 lanes -> 128 channels via float4
    const int grp  = threadIdx.x >> 5;   // 8 w-warps
    const int c4   = lane * 4;           // local channel base

    const float* __restrict__ base = g_xt + boff + half * HALF_C + c4;

    // ---- Phase 1: h-max per column, write colmax to smem ----
    if (hs < he) {
        #pragma unroll 1
        for (int w = ws0 + grp; w < we6; w += 8) {
            const float* p = base + hs * ROW_STRIDE + w * C_DIM;
            float m0 = -INFINITY, m1 = -INFINITY, m2 = -INFINITY, m3 = -INFINITY;
            int h = hs;
            for (; h + 1 < he; h += 2) {   // 2 independent loads in flight
                const float4 v0 = *(const float4*)p;
                const float4 v1 = *(const float4*)(p + ROW_STRIDE);
                m0 = fmaxf(fmaxf(m0, v0.x), v1.x);
                m1 = fmaxf(fmaxf(m1, v0.y), v1.y);
                m2 = fmaxf(fmaxf(m2, v0.z), v1.z);
                m3 = fmaxf(fmaxf(m3, v0.w), v1.w);
                p += 2 * ROW_STRIDE;
            }
            if (h < he) {
                const float4 v = *(const float4*)p;
                m0 = fmaxf(m0, v.x); m1 = fmaxf(m1, v.y);
                m2 = fmaxf(m2, v.z); m3 = fmaxf(m3, v.w);
            }
            *(float4*)&s_buf[w * HALF_C + c4] = make_float4(m0, m1, m2, m3);
        }
    }
    __syncthreads();

    // ---- Phase 2: per-bin w-max from smem ----
    float r0 = 0.0f, r1 = 0.0f, r2 = 0.0f, r3 = 0.0f;
    if (grp < PW) {
        const int ws = __ldg(&g_ws[roi * PW + grp]);
        const int we = __ldg(&g_we[roi * PW + grp]);
        if (hs < he && ws < we) {
            float m0 = -INFINITY, m1 = -INFINITY, m2 = -INFINITY, m3 = -INFINITY;
            #pragma unroll 1
            for (int w = ws; w < we; ++w) {
                const float4 v = *(const float4*)&s_buf[w * HALF_C + c4];
                m0 = fmaxf(m0, v.x); m1 = fmaxf(m1, v.y);
                m2 = fmaxf(m2, v.z); m3 = fmaxf(m3, v.w);
            }
            r0 = m0; r1 = m1; r2 = m2; r3 = m3;
        }
    }
    __syncthreads();

    // ---- Phase 3: stage [c_local][pw] and dump coalesced ----
    if (grp < PW) {
        s_buf[(c4 + 0) * PW + grp] = r0;
        s_buf[(c4 + 1) * PW + grp] = r1;
        s_buf[(c4 + 2) * PW + grp] = r2;
        s_buf[(c4 + 3) * PW + grp] = r3;
    }
    __syncthreads();

    float* __restrict__ obase = out + (size_t)roi * OUT_PER_ROI
                                    + (half * HALF_C) * NBINS + ph * PW;
    #pragma unroll 1
    for (int i = threadIdx.x; i < HALF_C * PW; i += 256) {
        const int c  = i / PW;
        const int pw = i - c * PW;
        obase[c * NBINS + pw] = s_buf[i];
    }
}

extern "C" void kernel_launch(void* const* d_in, const int* in_sizes, int n_in,
                              void* d_out, int out_size) {
    const float* x    = (const float*)d_in[0];
    const float* rois = (const float*)d_in[1];
    float* out        = (float*)d_out;

    (void)in_sizes; (void)n_in; (void)out_size;

    dim3 tgrid((HW + 31) / 32, C_DIM / 32, N_IMG);
    dim3 tblk(32, 32);
    transpose_kernel<<<tgrid, tblk>>>(x, rois);

    dim3 pgrid(N_ROI, PH, 2);
    roipool_kernel<<<pgrid, 256>>>(out);
}

// round 9
// speedup vs baseline: 1.2975x; 1.2975x over previous
#include <cuda_runtime.h>
#include <math.h>

// Problem constants
#define N_IMG 4
#define C_DIM 256
#define H_DIM 50
#define W_DIM 50
#define HW (H_DIM * W_DIM)
#define PH 7
#define PW 7
#define NBINS (PH * PW)
#define N_ROI 1024
#define OUT_PER_ROI (C_DIM * NBINS)   // 12544 floats
#define SPATIAL_SCALE 0.0625f
#define ROW_STRIDE (W_DIM * C_DIM)    // floats per h-row in NHWC

// fl(1/7) in fp32 — XLA rewrites (x / 7) into (x * fl(1/7)); we must match it.
#define RCP_7 0.14285714924335479736328125f

// Scratch: x transposed to [N][H][W][C] (channels-last) = 10.24 MB
__device__ float g_xt[N_IMG * HW * C_DIM];

// Precomputed per-roi geometry (ints, computed once with exact XLA numerics)
__device__ int g_boff[N_ROI];        // image base offset in floats
__device__ int g_hs[N_ROI * PH];
__device__ int g_he[N_ROI * PH];
__device__ int g_ws[N_ROI * PW];
__device__ int g_we[N_ROI * PW];

// ---------------------------------------------------------------------------
// Transpose NCHW -> NHWC via 32x32 smem tiles.
// Block (0,0,0) additionally precomputes all roi bin edges (1024 threads =
// 1024 rois) — zero extra launch, exact XLA numerics isolated here.
// ---------------------------------------------------------------------------
__global__ void __launch_bounds__(1024) transpose_kernel(const float* __restrict__ x,
                                                         const float* __restrict__ rois) {
    __shared__ float tile[32][33];

    if (blockIdx.x == 0 && blockIdx.y == 0 && blockIdx.z == 0) {
        const int roi = threadIdx.y * 32 + threadIdx.x;   // 0..1023
        const float* r = rois + roi * 5;
        const int b  = (int)r[0];
        const int xs = (int)rintf(__fmul_rn(r[1], SPATIAL_SCALE));
        const int ys = (int)rintf(__fmul_rn(r[2], SPATIAL_SCALE));
        const int xe = (int)rintf(__fmul_rn(r[3], SPATIAL_SCALE));
        const int ye = (int)rintf(__fmul_rn(r[4], SPATIAL_SCALE));
        const float rw = (float)max(xe - xs + 1, 1);
        const float rh = (float)max(ye - ys + 1, 1);
        const float bh = __fmul_rn(rh, RCP_7);   // XLA reciprocal-multiply
        const float bw = __fmul_rn(rw, RCP_7);

        g_boff[roi] = b * (HW * C_DIM);
        #pragma unroll
        for (int p = 0; p < PH; ++p) {
            int hs = (int)floorf(__fmul_rn((float)p,        bh)) + ys;
            int he = (int)ceilf (__fmul_rn((float)p + 1.0f, bh)) + ys;
            int ws = (int)floorf(__fmul_rn((float)p,        bw)) + xs;
            int we = (int)ceilf (__fmul_rn((float)p + 1.0f, bw)) + xs;
            g_hs[roi * PH + p] = min(max(hs, 0), H_DIM);
            g_he[roi * PH + p] = min(max(he, 0), H_DIM);
            g_ws[roi * PW + p] = min(max(ws, 0), W_DIM);
            g_we[roi * PW + p] = min(max(we, 0), W_DIM);
        }
    }

    const int n   = blockIdx.z;
    const int hw0 = blockIdx.x * 32;
    const int c0b = blockIdx.y * 32;
    {
        const int c  = c0b + threadIdx.y;
        const int hw = hw0 + threadIdx.x;
        if (hw < HW) {
            tile[threadIdx.y][threadIdx.x] = x[(n * C_DIM + c) * HW + hw];
        }
    }
    __syncthreads();
    {
        const int hw = hw0 + threadIdx.y;
        const int c  = c0b + threadIdx.x;
        if (hw < HW) {
            g_xt[(n * HW + hw) * C_DIM + c] = tile[threadIdx.x][threadIdx.y];
        }
    }
}

// ---------------------------------------------------------------------------
// RoI max pooling: one block per (roi, ph-row). Grid = 1024 x 7.
// Block = 256 threads = 4 pw-groups x 64 lanes (float4 -> 256 channels).
// Each pw-group handles pw = grp, then pw = grp + 4.
// Hot loop is a 2x2 (h,w) diamond: FOUR independent LDG.128 in flight
// per iteration (latency hiding vs ~240cyc L2 hits); warp-uniform control.
// ---------------------------------------------------------------------------
__global__ void __launch_bounds__(256, 6) roipool_kernel(float* __restrict__ out) {
    __shared__ float s_out[C_DIM * PW];   // [c][pw] = 7168 B

    const int roi = blockIdx.x;
    const int ph  = blockIdx.y;

    const int boff = __ldg(&g_boff[roi]);
    const int hs   = __ldg(&g_hs[roi * PH + ph]);
    const int he   = __ldg(&g_he[roi * PH + ph]);

    const int lane = threadIdx.x & 63;   // 64 lanes -> 256 channels via float4
    const int grp  = threadIdx.x >> 6;   // 4 pw-groups
    const int c0   = lane * 4;

    const float* __restrict__ base = g_xt + boff + c0;

    #pragma unroll 1
    for (int it = 0; it < 2; ++it) {
        const int pw = it * 4 + grp;
        if (pw < PW) {
            const int ws = __ldg(&g_ws[roi * PW + pw]);
            const int we = __ldg(&g_we[roi * PW + pw]);

            float m0 = -INFINITY, m1 = -INFINITY, m2 = -INFINITY, m3 = -INFINITY;
            const bool empty = (hs >= he) || (ws >= we);

            int h = hs;
            #pragma unroll 1
            for (; h + 1 < he; h += 2) {           // two rows per trip
                const float* p0 = base + h * ROW_STRIDE;
                const float* p1 = p0 + ROW_STRIDE;
                int w = ws;
                #pragma unroll 1
                for (; w + 1 < we; w += 2) {       // 2x2 diamond: 4 loads in flight
                    const float4 va = *(const float4*)(p0 + w * C_DIM);
                    const float4 vb = *(const float4*)(p0 + (w + 1) * C_DIM);
                    const float4 vc = *(const float4*)(p1 + w * C_DIM);
                    const float4 vd = *(const float4*)(p1 + (w + 1) * C_DIM);
                    m0 = fmaxf(fmaxf(fmaxf(m0, va.x), vb.x), fmaxf(vc.x, vd.x));
                    m1 = fmaxf(fmaxf(fmaxf(m1, va.y), vb.y), fmaxf(vc.y, vd.y));
                    m2 = fmaxf(fmaxf(fmaxf(m2, va.z), vb.z), fmaxf(vc.z, vd.z));
                    m3 = fmaxf(fmaxf(fmaxf(m3, va.w), vb.w), fmaxf(vc.w, vd.w));
                }
                if (w < we) {                      // odd-width remainder: 2 loads
                    const float4 va = *(const float4*)(p0 + w * C_DIM);
                    const float4 vc = *(const float4*)(p1 + w * C_DIM);
                    m0 = fmaxf(m0, fmaxf(va.x, vc.x));
                    m1 = fmaxf(m1, fmaxf(va.y, vc.y));
                    m2 = fmaxf(m2, fmaxf(va.z, vc.z));
                    m3 = fmaxf(m3, fmaxf(va.w, vc.w));
                }
            }
            if (h < he) {                          // odd-height remainder row
                const float* p0 = base + h * ROW_STRIDE;
                int w = ws;
                #pragma unroll 1
                for (; w + 1 < we; w += 2) {
                    const float4 va = *(const float4*)(p0 + w * C_DIM);
                    const float4 vb = *(const float4*)(p0 + (w + 1) * C_DIM);
                    m0 = fmaxf(m0, fmaxf(va.x, vb.x));
                    m1 = fmaxf(m1, fmaxf(va.y, vb.y));
                    m2 = fmaxf(m2, fmaxf(va.z, vb.z));
                    m3 = fmaxf(m3, fmaxf(va.w, vb.w));
                }
                if (w < we) {
                    const float4 va = *(const float4*)(p0 + w * C_DIM);
                    m0 = fmaxf(m0, va.x); m1 = fmaxf(m1, va.y);
                    m2 = fmaxf(m2, va.z); m3 = fmaxf(m3, va.w);
                }
            }
            if (empty) { m0 = m1 = m2 = m3 = 0.0f; }

            s_out[(c0 + 0) * PW + pw] = m0;
            s_out[(c0 + 1) * PW + pw] = m1;
            s_out[(c0 + 2) * PW + pw] = m2;
            s_out[(c0 + 3) * PW + pw] = m3;
        }
    }
    __syncthreads();

    // Store: out[roi, c, ph, pw] = s_out[c*7 + pw].
    float* __restrict__ obase = out + (size_t)roi * OUT_PER_ROI + ph * PW;
    #pragma unroll 1
    for (int i = threadIdx.x; i < C_DIM * PW; i += 256) {
        const int c  = i / PW;
        const int pw = i - c * PW;
        obase[c * NBINS + pw] = s_out[i];
    }
}

extern "C" void kernel_launch(void* const* d_in, const int* in_sizes, int n_in,
                              void* d_out, int out_size) {
    const float* x    = (const float*)d_in[0];
    const float* rois = (const float*)d_in[1];
    float* out        = (float*)d_out;

    (void)in_sizes; (void)n_in; (void)out_size;

    dim3 tgrid((HW + 31) / 32, C_DIM / 32, N_IMG);
    dim3 tblk(32, 32);
    transpose_kernel<<<tgrid, tblk>>>(x, rois);

    dim3 pgrid(N_ROI, PH);
    roipool_kernel<<<pgrid, 256>>>(out);
}